// round 16
// baseline (speedup 1.0000x reference)
#include <cuda_runtime.h>
#include <math.h>

#define EPS      1e-6f
#define HIT_TOL  1e-3f
#define MIN_LEN  1.2e-6f

#define BT  256                // block threads (8 warps)
#define PPB 64                 // paths per block -> 4x warp over-provisioning
#define NW  (BT / 32)
#define R2A_END 192            // 2a scans tris [0, min(NF,192)); tail split in 2b

struct V3 { float x, y, z; };

__device__ __forceinline__ V3 v3(float x, float y, float z) { V3 r; r.x=x; r.y=y; r.z=z; return r; }
__device__ __forceinline__ V3 vsub(V3 a, V3 b) { return v3(a.x-b.x, a.y-b.y, a.z-b.z); }
__device__ __forceinline__ V3 vadd(V3 a, V3 b) { return v3(a.x+b.x, a.y+b.y, a.z+b.z); }
__device__ __forceinline__ V3 vscale(V3 a, float s) { return v3(a.x*s, a.y*s, a.z*s); }
__device__ __forceinline__ float vdot(V3 a, V3 b) { return a.x*b.x + a.y*b.y + a.z*b.z; }
__device__ __forceinline__ V3 vcross(V3 a, V3 b) {
    return v3(a.y*b.z - a.z*b.y,
              a.z*b.x - a.x*b.z,
              a.x*b.y - a.y*b.x);
}

__device__ __forceinline__ V3 load_vert(const float* __restrict__ mv, int i) {
    return v3(__ldg(mv + 3*i), __ldg(mv + 3*i + 1), __ldg(mv + 3*i + 2));
}

struct Tri { V3 v0, e1, e2; };

__device__ __forceinline__ Tri load_tri(const float* __restrict__ mesh_v,
                                        const int*   __restrict__ mesh_t,
                                        int f)
{
    int i0 = __ldg(mesh_t + 3*f);
    int i1 = __ldg(mesh_t + 3*f + 1);
    int i2 = __ldg(mesh_t + 3*f + 2);
    V3 p0 = load_vert(mesh_v, i0);
    V3 p1 = load_vert(mesh_v, i1);
    V3 p2 = load_vert(mesh_v, i2);
    Tri t;
    t.v0 = p0;
    t.e1 = vsub(p1, p0);
    t.e2 = vsub(p2, p0);
    return t;
}

// Moller-Trumbore (scalar), mirroring the reference's exact predicate structure.
__device__ __forceinline__ bool mt_hit(V3 ro, V3 rd, const Tri& T, float& t_out)
{
    V3 h = vcross(rd, T.e2);
    float a = vdot(T.e1, h);
    bool cond_a = fabsf(a) < EPS;
    float f = cond_a ? 0.0f : (1.0f / a);
    V3 s = vsub(ro, T.v0);
    float u = f * vdot(s, h);
    V3 q = vcross(s, T.e1);
    float v = f * vdot(rd, q);
    float t = f * vdot(T.e2, q);
    t_out = t;
    return (!cond_a) && (u >= 0.0f) && (u <= 1.0f) && (v >= 0.0f) && (u + v <= 1.0f) && (t > EPS);
}

// Division-free MT hit-with-(EPS < t < lim): all predicates scaled by |a|.
__device__ __forceinline__ bool mt_blocks(V3 ro, V3 rd, const Tri& T, float lim)
{
    V3 h = vcross(rd, T.e2);
    float a = vdot(T.e1, h);
    float abs_a = fabsf(a);
    if (abs_a < EPS) return false;
    float sgn = (a >= 0.0f) ? 1.0f : -1.0f;
    V3 s = vsub(ro, T.v0);
    float su = sgn * vdot(s, h);
    V3 q = vcross(s, T.e1);
    float sv = sgn * vdot(rd, q);
    float st = sgn * vdot(T.e2, q);
    return (su >= 0.0f) && (su <= abs_a) &&
           (sv >= 0.0f) && (su + sv <= abs_a) &&
           (st > EPS * abs_a) && (st < lim * abs_a);
}

__device__ __forceinline__ bool blocks_path(const Tri& Tt, V3 a0, V3 a1, V3 a2,
                                            V3 d0, V3 d1, V3 d2, float lim)
{
    if (mt_blocks(a0, d0, Tt, lim)) return true;
    if (mt_blocks(a1, d1, Tt, lim)) return true;
    if (mt_blocks(a2, d2, Tt, lim)) return true;
    return false;
}

// ---------------------------------------------------------------------------
// Single fused kernel; 64 paths per 256-thread block (125 blocks, 1000 warps):
//   phase 1 : threads 0-63 do path math + premask + unconditional outputs;
//             survivors to SMEM
//   phase 2a: ALL 8 warps claim survivors round-robin; EARLY-EXIT scan of
//             tris [0,64) (register-prefetched) then [64,192) (one MLP-4
//             round). Most blocked survivors die here cheaply.
//   phase 2b: each still-alive survivor's tail [192,NF) is split into 8
//             disjoint slices, one per warp -- no warp owns a full scan.
// ---------------------------------------------------------------------------
__global__ void __launch_bounds__(BT)
fused_kernel(const float* __restrict__ mesh_v,
             const int*   __restrict__ mesh_t,
             const float* __restrict__ tx_v,
             const float* __restrict__ rx_v,
             const int*   __restrict__ pc,
             float*       __restrict__ out,
             int T, int R, int P, int NF)
{
    __shared__ int   s_cnt;
    __shared__ int   s_alive_cnt;
    __shared__ float s_pts[PPB][12];
    __shared__ int   s_blk[PPB];
    __shared__ short s_alive[PPB];

    const int nPaths = T * R * P;
    const int tid  = threadIdx.x;
    const int lane = tid & 31;
    const int wid  = tid >> 5;

    if (tid == 0) { s_cnt = 0; s_alive_cnt = 0; }

    // ---- prefetch occlusion tris [0,64): 2 per lane (all warps);
    //      overlaps the path-math chain / barrier wait ----
    const bool pf0_ok = (lane < NF);
    const bool pf1_ok = (lane + 32 < NF);
    Tri pfT0 = load_tri(mesh_v, mesh_t, pf0_ok ? lane : 0);
    Tri pfT1 = load_tri(mesh_v, mesh_t, pf1_ok ? lane + 32 : 0);

    __syncthreads();                       // counters visible

    // ---- phase 1: path math (threads 0..PPB-1) ----
    int  my_slot = -1;
    bool premask = false;
    int  idx = blockIdx.x * PPB + tid;
    const bool is_path = (tid < PPB) && (idx < nPaths);

    if (is_path) {
        const int t_idx = idx / (R * P);
        const int rem   = idx - t_idx * (R * P);
        const int r_idx = rem / P;
        const int p_idx = rem - r_idx * P;

        const int f0 = __ldg(pc + 2 * p_idx);
        const int f1 = __ldg(pc + 2 * p_idx + 1);

        Tri T0 = load_tri(mesh_v, mesh_t, f0);
        Tri T1 = load_tri(mesh_v, mesh_t, f1);

        V3 fn0 = vcross(T0.e1, T0.e2);
        V3 n0  = vscale(fn0, 1.0f / sqrtf(vdot(fn0, fn0)));
        V3 fn1 = vcross(T1.e1, T1.e2);
        V3 n1  = vscale(fn1, 1.0f / sqrtf(vdot(fn1, fn1)));

        V3 txv = v3(__ldg(tx_v + 3*t_idx), __ldg(tx_v + 3*t_idx + 1), __ldg(tx_v + 3*t_idx + 2));
        V3 rxv = v3(__ldg(rx_v + 3*r_idx), __ldg(rx_v + 3*r_idx + 1), __ldg(rx_v + 3*r_idx + 2));

        V3 mv0 = T0.v0, mv1 = T1.v0;

        V3 img0 = vsub(txv, vscale(n0, 2.0f * vdot(vsub(txv, mv0), n0)));
        V3 img1 = vsub(img0, vscale(n1, 2.0f * vdot(vsub(img0, mv1), n1)));

        V3 u1 = vsub(rxv, img1);
        float un1 = vdot(u1, n1);
        float vn1 = vdot(vsub(img1, mv1), n1);
        float tt1 = (un1 == 0.0f) ? 0.0f : (-vn1 / un1);
        V3 p1v = vadd(img1, vscale(u1, tt1));

        V3 u0 = vsub(p1v, img0);
        float un0 = vdot(u0, n0);
        float vn0 = vdot(vsub(img0, mv0), n0);
        float tt0 = (un0 == 0.0f) ? 0.0f : (-vn0 / un0);
        V3 p0v = vadd(img0, vscale(u0, tt0));

        V3 rd0 = vsub(p0v, txv);
        V3 rd1 = vsub(p1v, p0v);
        V3 rd2 = vsub(rxv, p1v);

        bool too_small = (vdot(rd0, rd0) < MIN_LEN) ||
                         (vdot(rd1, rd1) < MIN_LEN) ||
                         (vdot(rd2, rd2) < MIN_LEN);

        float tdum;
        bool inside = mt_hit(txv, rd0, T0, tdum) && mt_hit(p0v, rd1, T1, tdum);

        float dp0 = vdot(vsub(txv, mv0), n0);
        float dn0 = vdot(vsub(p1v, mv0), n0);
        float dp1 = vdot(vsub(p0v, mv1), n1);
        float dn1 = vdot(vsub(rxv, mv1), n1);
        bool valid_refl = (dp0 * dn0 >= 0.0f) && (dp1 * dn1 >= 0.0f);

        premask = inside && valid_refl && !too_small;

        // unconditional outputs now; stores overlap the occlusion phase
        float* fp = out + (size_t)idx * 12;
        ((float4*)fp)[0] = make_float4(txv.x, txv.y, txv.z, p0v.x);
        ((float4*)fp)[1] = make_float4(p0v.y, p0v.z, p1v.x, p1v.y);
        ((float4*)fp)[2] = make_float4(p1v.z, rxv.x, rxv.y, rxv.z);

        float* ob = out + (size_t)nPaths * 12 + (size_t)idx * 4;
        ((float4*)ob)[0] = make_float4((float)t_idx, (float)f0, (float)f1, (float)r_idx);

        if (premask) {
            my_slot = atomicAdd(&s_cnt, 1);
            s_blk[my_slot] = 0;
            float* p = s_pts[my_slot];
            p[0]=txv.x; p[1]=txv.y;  p[2]=txv.z;
            p[3]=p0v.x; p[4]=p0v.y;  p[5]=p0v.z;
            p[6]=p1v.x; p[7]=p1v.y;  p[8]=p1v.z;
            p[9]=rxv.x; p[10]=rxv.y; p[11]=rxv.z;
        }
    }
    __syncthreads();
    const int cnt = s_cnt;
    const float lim = 1.0f - HIT_TOL;
    const int e2a = min(NF, R2A_END);

    // ---- phase 2a: warps claim survivors round-robin; early-exit [0,e2a) ----
    for (int s = wid; s < cnt; s += NW) {
        const float* p = s_pts[s];
        V3 a0 = v3(p[0], p[1], p[2]);
        V3 a1 = v3(p[3], p[4], p[5]);
        V3 a2 = v3(p[6], p[7], p[8]);
        V3 a3 = v3(p[9], p[10], p[11]);
        V3 d0 = vsub(a1, a0);
        V3 d1 = vsub(a2, a1);
        V3 d2 = vsub(a3, a2);

        // round 0: 64 prefetched triangles, pure flops + one ballot
        bool b0 = (pf0_ok && blocks_path(pfT0, a0, a1, a2, d0, d1, d2, lim)) ||
                  (pf1_ok && blocks_path(pfT1, a0, a1, a2, d0, d1, d2, lim));
        bool blk = __any_sync(0xFFFFFFFFu, b0);

        // round 1: tris [64, e2a), one MLP-4 gather round
        if (!blk && e2a > 64) {
            int fA = 64 + lane;
            int fB = fA + 32;
            int fC = fA + 64;
            int fD = fA + 96;
            bool okA = fA < e2a, okB = fB < e2a, okC = fC < e2a, okD = fD < e2a;
            Tri TA = load_tri(mesh_v, mesh_t, okA ? fA : 0);
            Tri TB = load_tri(mesh_v, mesh_t, okB ? fB : 0);
            Tri TC = load_tri(mesh_v, mesh_t, okC ? fC : 0);
            Tri TD = load_tri(mesh_v, mesh_t, okD ? fD : 0);
            bool b = (okA && blocks_path(TA, a0, a1, a2, d0, d1, d2, lim)) ||
                     (okB && blocks_path(TB, a0, a1, a2, d0, d1, d2, lim)) ||
                     (okC && blocks_path(TC, a0, a1, a2, d0, d1, d2, lim)) ||
                     (okD && blocks_path(TD, a0, a1, a2, d0, d1, d2, lim));
            blk = __any_sync(0xFFFFFFFFu, b);
        }

        if (lane == 0) {
            if (blk) s_blk[s] = 1;
            else if (NF > R2A_END) {
                int a = atomicAdd(&s_alive_cnt, 1);
                s_alive[a] = (short)s;
            }
        }
    }
    __syncthreads();

    // ---- phase 2b: tail [R2A_END,NF) of each alive survivor split across
    //      the 8 warps (disjoint slices) -- no warp owns a full scan ----
    const int tail = NF - R2A_END;
    if (tail > 0) {
        const int acnt  = s_alive_cnt;
        const int slice = (tail + NW - 1) / NW;
        for (int a = 0; a < acnt; a++) {
            const int s = s_alive[a];
            if (*((volatile int*)&s_blk[s])) continue;   // opportunistic skip

            const float* p = s_pts[s];
            V3 a0 = v3(p[0], p[1], p[2]);
            V3 a1 = v3(p[3], p[4], p[5]);
            V3 a2 = v3(p[6], p[7], p[8]);
            V3 a3 = v3(p[9], p[10], p[11]);
            V3 d0 = vsub(a1, a0);
            V3 d1 = vsub(a2, a1);
            V3 d2 = vsub(a3, a2);

            const int start = R2A_END + wid * slice;
            const int end   = min(NF, start + slice);

            bool b = false;
            for (int f = start + lane; f < end; f += 32) {
                Tri Tt = load_tri(mesh_v, mesh_t, f);
                b |= blocks_path(Tt, a0, a1, a2, d0, d1, d2, lim);
            }
            if (__any_sync(0xFFFFFFFFu, b) && lane == 0)
                s_blk[s] = 1;                   // all writers write 1: race-free
        }
    }
    __syncthreads();

    // ---- final mask write ----
    if (is_path) {
        bool blocked = premask && (s_blk[my_slot] != 0);
        bool mask = premask && !blocked;
        out[(size_t)nPaths * 16 + idx] = mask ? 1.0f : 0.0f;
    }
}

// ---------------------------------------------------------------------------
extern "C" void kernel_launch(void* const* d_in, const int* in_sizes, int n_in,
                              void* d_out, int out_size)
{
    const float* mesh_v = (const float*)d_in[0];   // (NV, 3) f32
    const int*   mesh_t = (const int*)  d_in[1];   // (NF, 3) i32
    const float* tx_v   = (const float*)d_in[2];   // (T, 3)  f32
    const float* rx_v   = (const float*)d_in[3];   // (R, 3)  f32
    const int*   pc     = (const int*)  d_in[4];   // (P, 2)  i32

    const int NF = in_sizes[1] / 3;
    const int T  = in_sizes[2] / 3;
    const int R  = in_sizes[3] / 3;
    const int P  = in_sizes[4] / 2;   // ORDER = 2

    const int nPaths = T * R * P;
    const int blocks = (nPaths + PPB - 1) / PPB;
    fused_kernel<<<blocks, BT>>>(mesh_v, mesh_t, tx_v, rx_v, pc,
                                 (float*)d_out, T, R, P, NF);
}

// round 17
// speedup vs baseline: 1.0295x; 1.0295x over previous
#include <cuda_runtime.h>
#include <math.h>

#define EPS      1e-6f
#define HIT_TOL  1e-3f
#define MIN_LEN  1.2e-6f

struct V3 { float x, y, z; };

__device__ __forceinline__ V3 v3(float x, float y, float z) { V3 r; r.x=x; r.y=y; r.z=z; return r; }
__device__ __forceinline__ V3 vsub(V3 a, V3 b) { return v3(a.x-b.x, a.y-b.y, a.z-b.z); }
__device__ __forceinline__ V3 vadd(V3 a, V3 b) { return v3(a.x+b.x, a.y+b.y, a.z+b.z); }
__device__ __forceinline__ V3 vscale(V3 a, float s) { return v3(a.x*s, a.y*s, a.z*s); }
__device__ __forceinline__ float vdot(V3 a, V3 b) { return a.x*b.x + a.y*b.y + a.z*b.z; }
__device__ __forceinline__ V3 vcross(V3 a, V3 b) {
    return v3(a.y*b.z - a.z*b.y,
              a.z*b.x - a.x*b.z,
              a.x*b.y - a.y*b.x);
}
__device__ __forceinline__ V3 shfl_v3(V3 v, int src) {
    v.x = __shfl_sync(0xFFFFFFFFu, v.x, src);
    v.y = __shfl_sync(0xFFFFFFFFu, v.y, src);
    v.z = __shfl_sync(0xFFFFFFFFu, v.z, src);
    return v;
}

__device__ __forceinline__ V3 load_vert(const float* __restrict__ mv, int i) {
    return v3(__ldg(mv + 3*i), __ldg(mv + 3*i + 1), __ldg(mv + 3*i + 2));
}

struct Tri { V3 v0, e1, e2; };

__device__ __forceinline__ Tri load_tri(const float* __restrict__ mesh_v,
                                        const int*   __restrict__ mesh_t,
                                        int f)
{
    int i0 = __ldg(mesh_t + 3*f);
    int i1 = __ldg(mesh_t + 3*f + 1);
    int i2 = __ldg(mesh_t + 3*f + 2);
    V3 p0 = load_vert(mesh_v, i0);
    V3 p1 = load_vert(mesh_v, i1);
    V3 p2 = load_vert(mesh_v, i2);
    Tri t;
    t.v0 = p0;
    t.e1 = vsub(p1, p0);
    t.e2 = vsub(p2, p0);
    return t;
}

// Moller-Trumbore (scalar), mirroring the reference's exact predicate structure.
// Premask path only (correctness-sensitive, unchanged from the passing kernel).
__device__ __forceinline__ bool mt_hit(V3 ro, V3 rd, const Tri& T, float& t_out)
{
    V3 h = vcross(rd, T.e2);
    float a = vdot(T.e1, h);
    bool cond_a = fabsf(a) < EPS;
    float f = cond_a ? 0.0f : (1.0f / a);
    V3 s = vsub(ro, T.v0);
    float u = f * vdot(s, h);
    V3 q = vcross(s, T.e1);
    float v = f * vdot(rd, q);
    float t = f * vdot(T.e2, q);
    t_out = t;
    return (!cond_a) && (u >= 0.0f) && (u <= 1.0f) && (v >= 0.0f) && (u + v <= 1.0f) && (t > EPS);
}

// Division-free MT hit-with-(EPS < t < lim): all predicates scaled by |a|.
__device__ __forceinline__ bool mt_blocks(V3 ro, V3 rd, const Tri& T, float lim)
{
    V3 h = vcross(rd, T.e2);
    float a = vdot(T.e1, h);
    float abs_a = fabsf(a);
    if (abs_a < EPS) return false;
    float sgn = (a >= 0.0f) ? 1.0f : -1.0f;
    V3 s = vsub(ro, T.v0);
    float su = sgn * vdot(s, h);
    V3 q = vcross(s, T.e1);
    float sv = sgn * vdot(rd, q);
    float st = sgn * vdot(T.e2, q);
    return (su >= 0.0f) && (su <= abs_a) &&
           (sv >= 0.0f) && (su + sv <= abs_a) &&
           (st > EPS * abs_a) && (st < lim * abs_a);
}

__device__ __forceinline__ bool blocks_path(const Tri& Tt, V3 a0, V3 a1, V3 a2,
                                            V3 d0, V3 d1, V3 d2, float lim)
{
    if (mt_blocks(a0, d0, Tt, lim)) return true;
    if (mt_blocks(a1, d1, Tt, lim)) return true;
    if (mt_blocks(a2, d2, Tt, lim)) return true;
    return false;
}

// ---------------------------------------------------------------------------
// Single fused kernel (R6 champion structure): one thread per (t,r,p) path,
// warp-autonomous, no block barriers. Per survivor:
//   mini-round 0/1/2: prefetched tris [0,32) vs ONE segment each
//                     (cheapest possible early-exit granularity, pure regs)
//   rounds k>0      : 128 triangles, 4 gathers per lane (MLP=4), 3 segments
// __any_sync early exit after every (mini-)round.
// ---------------------------------------------------------------------------
__global__ void __launch_bounds__(128)
fused_kernel(const float* __restrict__ mesh_v,
             const int*   __restrict__ mesh_t,
             const float* __restrict__ tx_v,
             const float* __restrict__ rx_v,
             const int*   __restrict__ pc,
             float*       __restrict__ out,
             int T, int R, int P, int NF)
{
    const int nPaths = T * R * P;
    int idx = blockIdx.x * blockDim.x + threadIdx.x;
    const bool valid = (idx < nPaths);
    if (idx >= nPaths) idx = nPaths - 1;       // clamp; keep warp converged
    const int lane = threadIdx.x & 31;

    // ---- prefetch occlusion tris [0,32): 1 per lane; issued first so the
    //      gather latency overlaps the dependent path-math chain ----
    const bool pf_ok = (lane < NF);
    Tri pfT = load_tri(mesh_v, mesh_t, pf_ok ? lane : 0);

    // decode (t, r, p) -- row-major (T, R, P)
    const int t_idx = idx / (R * P);
    const int rem   = idx - t_idx * (R * P);
    const int r_idx = rem / P;
    const int p_idx = rem - r_idx * P;

    const int f0 = __ldg(pc + 2 * p_idx);
    const int f1 = __ldg(pc + 2 * p_idx + 1);

    Tri T0 = load_tri(mesh_v, mesh_t, f0);
    Tri T1 = load_tri(mesh_v, mesh_t, f1);

    // unit normals (match reference: fn / ||fn||)
    V3 fn0 = vcross(T0.e1, T0.e2);
    V3 n0  = vscale(fn0, 1.0f / sqrtf(vdot(fn0, fn0)));
    V3 fn1 = vcross(T1.e1, T1.e2);
    V3 n1  = vscale(fn1, 1.0f / sqrtf(vdot(fn1, fn1)));

    V3 txv = v3(__ldg(tx_v + 3*t_idx), __ldg(tx_v + 3*t_idx + 1), __ldg(tx_v + 3*t_idx + 2));
    V3 rxv = v3(__ldg(rx_v + 3*r_idx), __ldg(rx_v + 3*r_idx + 1), __ldg(rx_v + 3*r_idx + 2));

    V3 mv0 = T0.v0, mv1 = T1.v0;

    // forward scan: images
    V3 img0 = vsub(txv, vscale(n0, 2.0f * vdot(vsub(txv, mv0), n0)));
    V3 img1 = vsub(img0, vscale(n1, 2.0f * vdot(vsub(img0, mv1), n1)));

    // backward scan: reflection points
    V3 u1 = vsub(rxv, img1);
    float un1 = vdot(u1, n1);
    float vn1 = vdot(vsub(img1, mv1), n1);
    float tt1 = (un1 == 0.0f) ? 0.0f : (-vn1 / un1);
    V3 p1v = vadd(img1, vscale(u1, tt1));

    V3 u0 = vsub(p1v, img0);
    float un0 = vdot(u0, n0);
    float vn0 = vdot(vsub(img0, mv0), n0);
    float tt0 = (un0 == 0.0f) ? 0.0f : (-vn0 / un0);
    V3 p0v = vadd(img0, vscale(u0, tt0));

    // segments
    V3 rd0 = vsub(p0v, txv);
    V3 rd1 = vsub(p1v, p0v);
    V3 rd2 = vsub(rxv, p1v);

    bool too_small = (vdot(rd0, rd0) < MIN_LEN) ||
                     (vdot(rd1, rd1) < MIN_LEN) ||
                     (vdot(rd2, rd2) < MIN_LEN);

    float tdum;
    bool inside = mt_hit(txv, rd0, T0, tdum) && mt_hit(p0v, rd1, T1, tdum);

    float dp0 = vdot(vsub(txv, mv0), n0);
    float dn0 = vdot(vsub(p1v, mv0), n0);
    float dp1 = vdot(vsub(p0v, mv1), n1);
    float dn1 = vdot(vsub(rxv, mv1), n1);
    bool valid_refl = (dp0 * dn0 >= 0.0f) && (dp1 * dn1 >= 0.0f);

    bool premask = inside && valid_refl && !too_small && valid;

    // write the unconditional outputs NOW so stores overlap occlusion
    if (valid) {
        float* fp = out + (size_t)idx * 12;
        ((float4*)fp)[0] = make_float4(txv.x, txv.y, txv.z, p0v.x);
        ((float4*)fp)[1] = make_float4(p0v.y, p0v.z, p1v.x, p1v.y);
        ((float4*)fp)[2] = make_float4(p1v.z, rxv.x, rxv.y, rxv.z);

        float* ob = out + (size_t)nPaths * 12 + (size_t)idx * 4;
        ((float4*)ob)[0] = make_float4((float)t_idx, (float)f0, (float)f1, (float)r_idx);
    }

    // ---- warp-cooperative occlusion for survivors ----
    bool blocked = false;
    unsigned ball = __ballot_sync(0xFFFFFFFFu, premask);
    const float lim = 1.0f - HIT_TOL;
    while (ball) {
        const int src = __ffs(ball) - 1;
        ball &= ball - 1;
        V3 a0 = shfl_v3(txv, src);
        V3 a1 = shfl_v3(p0v, src);
        V3 a2 = shfl_v3(p1v, src);
        V3 a3 = shfl_v3(rxv, src);
        V3 d0 = vsub(a1, a0);
        V3 d1 = vsub(a2, a1);
        V3 d2 = vsub(a3, a2);

        // mini-rounds: prefetched 32 tris, ONE segment per ballot
        bool blk;
        {
            bool b = pf_ok && mt_blocks(a0, d0, pfT, lim);
            blk = __any_sync(0xFFFFFFFFu, b);
        }
        if (!blk) {
            bool b = pf_ok && mt_blocks(a1, d1, pfT, lim);
            blk = __any_sync(0xFFFFFFFFu, b);
        }
        if (!blk) {
            bool b = pf_ok && mt_blocks(a2, d2, pfT, lim);
            blk = __any_sync(0xFFFFFFFFu, b);
        }

        // escalation rounds: 128 triangles per round, MLP=4 gathers, 3 segs
        if (!blk) {
            for (int base = 32; base < NF && !blk; base += 128) {
                int fA = base + lane;
                int fB = fA + 32;
                int fC = fA + 64;
                int fD = fA + 96;
                bool okA = fA < NF, okB = fB < NF, okC = fC < NF, okD = fD < NF;
                Tri TA = load_tri(mesh_v, mesh_t, okA ? fA : 0);
                Tri TB = load_tri(mesh_v, mesh_t, okB ? fB : 0);
                Tri TC = load_tri(mesh_v, mesh_t, okC ? fC : 0);
                Tri TD = load_tri(mesh_v, mesh_t, okD ? fD : 0);
                bool b = (okA && blocks_path(TA, a0, a1, a2, d0, d1, d2, lim)) ||
                         (okB && blocks_path(TB, a0, a1, a2, d0, d1, d2, lim)) ||
                         (okC && blocks_path(TC, a0, a1, a2, d0, d1, d2, lim)) ||
                         (okD && blocks_path(TD, a0, a1, a2, d0, d1, d2, lim));
                blk = __any_sync(0xFFFFFFFFu, b);
            }
        }
        if (lane == src) blocked = blk;
    }

    bool mask = premask && !blocked;

    if (valid)
        out[(size_t)nPaths * 16 + idx] = mask ? 1.0f : 0.0f;
}

// ---------------------------------------------------------------------------
extern "C" void kernel_launch(void* const* d_in, const int* in_sizes, int n_in,
                              void* d_out, int out_size)
{
    const float* mesh_v = (const float*)d_in[0];   // (NV, 3) f32
    const int*   mesh_t = (const int*)  d_in[1];   // (NF, 3) i32
    const float* tx_v   = (const float*)d_in[2];   // (T, 3)  f32
    const float* rx_v   = (const float*)d_in[3];   // (R, 3)  f32
    const int*   pc     = (const int*)  d_in[4];   // (P, 2)  i32

    const int NF = in_sizes[1] / 3;
    const int T  = in_sizes[2] / 3;
    const int R  = in_sizes[3] / 3;
    const int P  = in_sizes[4] / 2;   // ORDER = 2

    const int nPaths = T * R * P;
    const int threads = 128;
    const int blocks = (nPaths + threads - 1) / threads;
    fused_kernel<<<blocks, threads>>>(mesh_v, mesh_t, tx_v, rx_v, pc,
                                      (float*)d_out, T, R, P, NF);
}